// round 8
// baseline (speedup 1.0000x reference)
#include <cuda_runtime.h>

#define G 128
#define H 64
#define Q 32

// ---------------- constant weights (uniform compile-time access only) -------
__constant__ float cWt1[2*2*2*4*16];    // (2,2,2,4,16)
__constant__ float cWt2[2*2*2*16];      // (2,2,2,16,1)

// ---------------- scratch (device globals; no allocs allowed) ---------------
__device__ float g_hp1[2u*64*64*64*16]; // pooled stage-1 activations, NDHWC
__device__ float g_hp2[2u*32*32*32*4];  // pooled stage-2 activations, NDHWC
__device__ unsigned char g_m1[2u*64*64*64];
__device__ unsigned char g_m2[2u*32*32*32];

__device__ __forceinline__ float frelu(float v) { return v > 0.f ? v : 0.f; }
__device__ __forceinline__ float fsig(float v) { return 1.f / (1.f + __expf(-v)); }

// packed fp32x2 helpers (Blackwell FFMA2 — only reachable via PTX)
__device__ __forceinline__ unsigned long long dup2(float a) {
    unsigned long long r;
    asm("mov.b64 %0, {%1, %1};" : "=l"(r) : "f"(a));
    return r;
}
__device__ __forceinline__ void fma2(unsigned long long& d,
                                     unsigned long long a, unsigned long long b) {
    asm("fma.rn.f32x2 %0, %1, %2, %0;" : "+l"(d) : "l"(a), "l"(b));
}

// ============================================================================
// K1: xm = x*(occ==0); h1 = relu(conv3(xm,W1))*m0; hp1 = maxpool2(h1)
// Active-voxel compaction -> dense conv passes (no divergent per-child branch).
// Weights in registers (27/thread, lane = channel). Also emits m1 bytes.
// ============================================================================
__global__ __launch_bounds__(256) void k1_conv1_pool(const float* __restrict__ x,
                                                     const int* __restrict__ occ,
                                                     const float* __restrict__ W1)
{
    __shared__ float xs[1000];              // 10^3 masked-x halo
    __shared__ unsigned short lst[512];     // compacted active fine voxels
    __shared__ int cnt;
    __shared__ int cellact[64];             // any-active per pooled cell
    __shared__ float pl[1024];              // pooled accum [cell][ch]

    int bi  = blockIdx.x;
    int b   = bi >> 12;
    int tz  = (bi >> 8) & 15, ty = (bi >> 4) & 15, tx = bi & 15;
    int tid = threadIdx.x;
    int ch  = tid & 15;
    int g   = tid >> 4;

    // per-thread weights for this thread's output channel (W1: [tap][1][16])
    float w[27];
    #pragma unroll
    for (int t = 0; t < 27; t++) w[t] = W1[t*16 + ch];

    if (tid == 0) cnt = 0;
    if (tid < 64) cellact[tid] = 0;
    #pragma unroll
    for (int it = 0; it < 4; it++) pl[tid + it*256] = 0.f;
    __syncthreads();

    int fz0 = tz*8, fy0 = ty*8, fx0 = tx*8;
    int baseb = b * (G*G*G);

    #pragma unroll
    for (int it = 0; it < 4; it++) {
        int i = tid + it*256;
        if (i < 1000) {
            int z = i/100, y = (i/10)%10, xx = i%10;
            int gz = fz0+z-1, gy = fy0+y-1, gx = fx0+xx-1;
            float v = 0.f;
            int   o = 1;
            bool inb = ((unsigned)gz < G) & ((unsigned)gy < G) & ((unsigned)gx < G);
            if (inb) {
                int idx = baseb + (gz*G + gy)*G + gx;
                o = occ[idx];
                v = x[idx];
            }
            bool act = inb && (o == 0);
            xs[i] = act ? v : 0.f;
            if (act && z >= 1 && z <= 8 && y >= 1 && y <= 8 && xx >= 1 && xx <= 8) {
                int lz = z-1, ly = y-1, lx = xx-1;
                int p = atomicAdd(&cnt, 1);
                lst[p] = (unsigned short)((lz<<6) | (ly<<3) | lx);
                atomicOr(&cellact[((lz>>1)<<4) | ((ly>>1)<<2) | (lx>>1)], 1);
            }
        }
    }
    __syncthreads();

    int n = cnt;
    // dense passes: 16 voxels per pass, 16 threads (=channels) per voxel
    for (int base = 0; base < n; base += 16) {
        int vi = base + g;
        if (vi < n) {
            int code = lst[vi];
            int lz = code >> 6, ly = (code >> 3) & 7, lx = code & 7;
            const float* xp = &xs[lz*100 + ly*10 + lx];
            float acc = 0.f;
            #pragma unroll
            for (int dz = 0; dz < 3; dz++)
            #pragma unroll
            for (int dy = 0; dy < 3; dy++)
            #pragma unroll
            for (int dx = 0; dx < 3; dx++)
                acc = fmaf(xp[dz*100 + dy*10 + dx], w[(dz*3+dy)*3+dx], acc);
            acc = frelu(acc);
            int cell = ((lz>>1)<<4) | ((ly>>1)<<2) | (lx>>1);
            atomicMax((int*)&pl[cell*16 + ch], __float_as_int(acc)); // nonneg floats
        }
    }
    __syncthreads();

    #pragma unroll
    for (int it = 0; it < 4; it++) {
        int i = tid + it*256;
        int cell = i >> 4, c2 = i & 15;
        int cz = cell >> 4, cy = (cell >> 2) & 3, cx = cell & 3;
        int pz = tz*4 + cz, py = ty*4 + cy, px = tx*4 + cx;
        int pidx = ((b*H + pz)*H + py)*H + px;
        g_hp1[(pidx << 4) + c2] = pl[i];
        if (c2 == 0) g_m1[pidx] = (unsigned char)(cellact[cell] != 0);
    }
}

// ============================================================================
// K2: h2 = relu(conv3(hp1,W2))*m1; hp2 = maxpool2(h2); also emits m2.
// 256 threads, thread = (lz2,ly,lx) handling voxels z=lz2 and z=lz2+4.
// Weights in SHARED memory pre-packed as f32x2 co-pairs; inner loop uses
// fma.rn.f32x2 (2x fp32 fma throughput). m1 comes from g_m1 bytes.
// ============================================================================
__global__ __launch_bounds__(256) void k2_conv2_pool(const float* __restrict__ W2)
{
    extern __shared__ float ts[];            // 10*10*10*16 floats = 64000 B
    __shared__ unsigned long long ws[864];   // [tap][ci][co-pair] packed
    __shared__ float hs[512*4];              // per-voxel relu'd masked outputs
    __shared__ unsigned char sm1[512];       // per-voxel m1

    int bi  = blockIdx.x;
    int b   = bi >> 9;
    int t   = bi & 511;
    int tz  = t >> 6, ty = (t >> 3) & 7, tx = t & 7;
    int tid = threadIdx.x;

    int fz0 = tz*8, fy0 = ty*8, fx0 = tx*8;

    // weights: W2 is (27,16,4) floats -> 864 aligned f32 pairs
    const unsigned long long* W2p = (const unsigned long long*)W2;
    for (int i = tid; i < 864; i += 256) ws[i] = W2p[i];

    // halo load
    for (int i = tid; i < 1000; i += 256) {
        int z = i/100, y = (i/10)%10, xx = i%10;
        int gz = fz0+z-1, gy = fy0+y-1, gx = fx0+xx-1;
        float4* dst = (float4*)&ts[i*16];
        if ((unsigned)gz < H && (unsigned)gy < H && (unsigned)gx < H) {
            const float4* src = (const float4*)&g_hp1[(((b*H+gz)*H + gy)*H + gx)*16];
            dst[0] = src[0]; dst[1] = src[1]; dst[2] = src[2]; dst[3] = src[3];
        } else {
            float4 zz = make_float4(0.f, 0.f, 0.f, 0.f);
            dst[0] = zz; dst[1] = zz; dst[2] = zz; dst[3] = zz;
        }
    }
    __syncthreads();

    int lz2 = tid >> 6, ly = (tid >> 3) & 7, lx = tid & 7;
    int uz0 = fz0 + lz2, uz1 = uz0 + 4, uy = fy0 + ly, ux = fx0 + lx;

    unsigned char m1_0 = g_m1[((b*H + uz0)*H + uy)*H + ux];
    unsigned char m1_1 = g_m1[((b*H + uz1)*H + uy)*H + ux];

    unsigned long long a00 = 0ull, a01 = 0ull;   // vox0: (co0,co1),(co2,co3)
    unsigned long long a10 = 0ull, a11 = 0ull;   // vox1

    if (m1_0 | m1_1) {
        #pragma unroll 1
        for (int dz = 0; dz < 3; dz++) {
            #pragma unroll 1
            for (int dy = 0; dy < 3; dy++) {
                int r0 = ((lz2+dz)*100 + (ly+dy)*10 + lx)*16;
                int wb = (dz*3 + dy)*3*32;
                #pragma unroll
                for (int dx = 0; dx < 3; dx++) {
                    const float* ip0 = &ts[r0 + dx*16];
                    const unsigned long long* wp = &ws[wb + dx*32];
                    #pragma unroll
                    for (int cq = 0; cq < 4; cq++) {
                        float va[4], vb[4];
                        *(float4*)va = *(const float4*)(ip0 + cq*4);
                        *(float4*)vb = *(const float4*)(ip0 + 6400 + cq*4);
                        #pragma unroll
                        for (int j = 0; j < 4; j++) {
                            unsigned long long w0 = wp[(cq*4+j)*2 + 0];
                            unsigned long long w1 = wp[(cq*4+j)*2 + 1];
                            unsigned long long d0 = dup2(va[j]);
                            unsigned long long d1 = dup2(vb[j]);
                            fma2(a00, d0, w0); fma2(a01, d0, w1);
                            fma2(a10, d1, w0); fma2(a11, d1, w1);
                        }
                    }
                }
            }
        }
    }

    int v0 = (lz2 << 6) | (ly << 3) | lx;
    int v1 = v0 + (4 << 6);
    {
        float o0 = m1_0 ? frelu(__uint_as_float((unsigned)(a00      ))) : 0.f;
        float o1 = m1_0 ? frelu(__uint_as_float((unsigned)(a00 >> 32))) : 0.f;
        float o2 = m1_0 ? frelu(__uint_as_float((unsigned)(a01      ))) : 0.f;
        float o3 = m1_0 ? frelu(__uint_as_float((unsigned)(a01 >> 32))) : 0.f;
        *(float4*)&hs[v0*4] = make_float4(o0, o1, o2, o3);
        o0 = m1_1 ? frelu(__uint_as_float((unsigned)(a10      ))) : 0.f;
        o1 = m1_1 ? frelu(__uint_as_float((unsigned)(a10 >> 32))) : 0.f;
        o2 = m1_1 ? frelu(__uint_as_float((unsigned)(a11      ))) : 0.f;
        o3 = m1_1 ? frelu(__uint_as_float((unsigned)(a11 >> 32))) : 0.f;
        *(float4*)&hs[v1*4] = make_float4(o0, o1, o2, o3);
    }
    sm1[v0] = m1_0;
    sm1[v1] = m1_1;
    __syncthreads();

    // pool 2x2x2 + m2
    {
        int cell = tid >> 2, co = tid & 3;
        int cz = cell >> 4, cy = (cell >> 2) & 3, cx = cell & 3;
        float mv = 0.f;
        int anym = 0;
        #pragma unroll
        for (int k = 0; k < 8; k++) {
            int child = (((cz*2 + ((k>>2)&1)) << 6) |
                         ((cy*2 + ((k>>1)&1)) << 3) |
                          (cx*2 + (k&1)));
            mv = fmaxf(mv, hs[child*4 + co]);
            anym |= sm1[child];
        }
        int pz = tz*4 + cz, py = ty*4 + cy, px = tx*4 + cx;
        int cidx = ((b*Q + pz)*Q + py)*Q + px;
        g_hp2[cidx*4 + co] = mv;
        if (co == 0) g_m2[cidx] = (unsigned char)(anym != 0);
    }
}

// ============================================================================
// K3: fused decoder; m2 from g_m2 (no occ traffic). Direct float4 stores.
//   h3(2i+d,co) = relu(sum_ci hp2(i,ci)*Wt1[1-d][ci][co])   (conv_transpose flip)
//   out(2u+e)   = sigmoid(sum_co h3(u,co)*Wt2[1-e][co]) * m
// ============================================================================
__global__ __launch_bounds__(256) void k3_tconv(float* __restrict__ out)
{
    int gid = blockIdx.x*256 + threadIdx.x;
    int b  = gid >> 15;
    int c  = gid & 32767;
    int iz = c >> 10, iy = (c >> 5) & 31, ix = c & 31;

    int obase = ((b*G + 4*iz)*G + 4*iy)*G + 4*ix;

    if (!g_m2[gid]) {
        float4 zz = make_float4(0.f, 0.f, 0.f, 0.f);
        #pragma unroll
        for (int r = 0; r < 16; r++) {
            int wz = r >> 2, wy = r & 3;
            *(float4*)&out[obase + (wz*G + wy)*G] = zz;
        }
        return;
    }

    const float4 hin = *(const float4*)&g_hp2[gid*4];

    #pragma unroll
    for (int dz = 0; dz < 2; dz++)
    #pragma unroll
    for (int dy = 0; dy < 2; dy++) {
        float h3a[16], h3b[16];
        {
            const float* wA = &cWt1[(((1-dz)*2 + (1-dy))*2 + 1)*64]; // dx=0
            const float* wB = &cWt1[(((1-dz)*2 + (1-dy))*2 + 0)*64]; // dx=1
            #pragma unroll
            for (int co = 0; co < 16; co++) {
                float va = fmaf(hin.x, wA[co],
                           fmaf(hin.y, wA[16+co],
                           fmaf(hin.z, wA[32+co], hin.w * wA[48+co])));
                float vb = fmaf(hin.x, wB[co],
                           fmaf(hin.y, wB[16+co],
                           fmaf(hin.z, wB[32+co], hin.w * wB[48+co])));
                h3a[co] = frelu(va);
                h3b[co] = frelu(vb);
            }
        }
        #pragma unroll
        for (int ez = 0; ez < 2; ez++)
        #pragma unroll
        for (int ey = 0; ey < 2; ey++) {
            const float* w2e0 = &cWt2[((((1-ez)*2 + (1-ey))*2) + 1)*16]; // ex=0
            const float* w2e1 = &cWt2[((((1-ez)*2 + (1-ey))*2) + 0)*16]; // ex=1
            float sx = 0.f, sy = 0.f, sz = 0.f, sw = 0.f;
            #pragma unroll
            for (int co = 0; co < 16; co++) {
                sx = fmaf(h3a[co], w2e0[co], sx);
                sy = fmaf(h3a[co], w2e1[co], sy);
                sz = fmaf(h3b[co], w2e0[co], sz);
                sw = fmaf(h3b[co], w2e1[co], sw);
            }
            float4 o = make_float4(fsig(sx), fsig(sy), fsig(sz), fsig(sw));
            int wz = 2*dz + ez, wy = 2*dy + ey;
            *(float4*)&out[obase + (wz*G + wy)*G] = o;
        }
    }
}

// ============================================================================
extern "C" void kernel_launch(void* const* d_in, const int* in_sizes, int n_in,
                              void* d_out, int out_size)
{
    const float* x   = (const float*)d_in[0];
    const float* W1  = (const float*)d_in[1];
    const float* W2  = (const float*)d_in[2];
    const float* Wt1 = (const float*)d_in[3];
    const float* Wt2 = (const float*)d_in[4];
    const int*   occ = (const int*)  d_in[5];

    int B = in_sizes[0] / (G*G*G);

    cudaMemcpyToSymbolAsync(cWt1, Wt1, 2*2*2*4*16*sizeof(float), 0, cudaMemcpyDeviceToDevice, 0);
    cudaMemcpyToSymbolAsync(cWt2, Wt2, 2*2*2*16*sizeof(float),   0, cudaMemcpyDeviceToDevice, 0);

    cudaFuncSetAttribute(k2_conv2_pool, cudaFuncAttributeMaxDynamicSharedMemorySize, 64000);

    k1_conv1_pool<<<B*4096, 256>>>(x, occ, W1);
    k2_conv2_pool<<<B*512, 256, 64000>>>(W2);
    k3_tconv<<<B*128, 256>>>((float*)d_out);
}

// round 9
// speedup vs baseline: 1.5848x; 1.5848x over previous
#include <cuda_runtime.h>

#define G 128
#define H 64
#define Q 32

// ---------------- constant weights (uniform-index access only) --------------
__constant__ float cW2[3*3*3*16*4];     // (3,3,3,16,4) = 1728
__constant__ float cWt1[2*2*2*4*16];    // (2,2,2,4,16)
__constant__ float cWt2[2*2*2*16];      // (2,2,2,16,1)

// ---------------- scratch (device globals; no allocs allowed) ---------------
__device__ float g_hp1[2u*64*64*64*16]; // pooled stage-1 activations, NDHWC
__device__ float g_hp2[2u*32*32*32*4];  // pooled stage-2 activations, NDHWC
__device__ unsigned char g_m1[2u*64*64*64];
__device__ unsigned char g_m2[2u*32*32*32];

__device__ __forceinline__ float frelu(float v) { return v > 0.f ? v : 0.f; }
__device__ __forceinline__ float fsig(float v) { return 1.f / (1.f + __expf(-v)); }

// packed fp32x2 helpers (Blackwell FFMA2 — only reachable via PTX)
__device__ __forceinline__ unsigned long long dup2(float a) {
    unsigned long long r;
    asm("mov.b64 %0, {%1, %1};" : "=l"(r) : "f"(a));
    return r;
}
__device__ __forceinline__ void fma2(unsigned long long& d,
                                     unsigned long long a, unsigned long long b) {
    asm("fma.rn.f32x2 %0, %1, %2, %0;" : "+l"(d) : "l"(a), "l"(b));
}

// ============================================================================
// K1: xm = x*(occ==0); h1 = relu(conv3(xm,W1))*m0; hp1 = maxpool2(h1)
// Active-voxel compaction -> dense conv passes. Weights in registers
// (27/thread, lane = channel). Emits m1 bytes. (unchanged from R8: 57.7us)
// ============================================================================
__global__ __launch_bounds__(256) void k1_conv1_pool(const float* __restrict__ x,
                                                     const int* __restrict__ occ,
                                                     const float* __restrict__ W1)
{
    __shared__ float xs[1000];              // 10^3 masked-x halo
    __shared__ unsigned short lst[512];     // compacted active fine voxels
    __shared__ int cnt;
    __shared__ int cellact[64];             // any-active per pooled cell
    __shared__ float pl[1024];              // pooled accum [cell][ch]

    int bi  = blockIdx.x;
    int b   = bi >> 12;
    int tz  = (bi >> 8) & 15, ty = (bi >> 4) & 15, tx = bi & 15;
    int tid = threadIdx.x;
    int ch  = tid & 15;
    int g   = tid >> 4;

    float w[27];
    #pragma unroll
    for (int t = 0; t < 27; t++) w[t] = W1[t*16 + ch];

    if (tid == 0) cnt = 0;
    if (tid < 64) cellact[tid] = 0;
    #pragma unroll
    for (int it = 0; it < 4; it++) pl[tid + it*256] = 0.f;
    __syncthreads();

    int fz0 = tz*8, fy0 = ty*8, fx0 = tx*8;
    int baseb = b * (G*G*G);

    #pragma unroll
    for (int it = 0; it < 4; it++) {
        int i = tid + it*256;
        if (i < 1000) {
            int z = i/100, y = (i/10)%10, xx = i%10;
            int gz = fz0+z-1, gy = fy0+y-1, gx = fx0+xx-1;
            float v = 0.f;
            int   o = 1;
            bool inb = ((unsigned)gz < G) & ((unsigned)gy < G) & ((unsigned)gx < G);
            if (inb) {
                int idx = baseb + (gz*G + gy)*G + gx;
                o = occ[idx];
                v = x[idx];
            }
            bool act = inb && (o == 0);
            xs[i] = act ? v : 0.f;
            if (act && z >= 1 && z <= 8 && y >= 1 && y <= 8 && xx >= 1 && xx <= 8) {
                int lz = z-1, ly = y-1, lx = xx-1;
                int p = atomicAdd(&cnt, 1);
                lst[p] = (unsigned short)((lz<<6) | (ly<<3) | lx);
                atomicOr(&cellact[((lz>>1)<<4) | ((ly>>1)<<2) | (lx>>1)], 1);
            }
        }
    }
    __syncthreads();

    int n = cnt;
    for (int base = 0; base < n; base += 16) {
        int vi = base + g;
        if (vi < n) {
            int code = lst[vi];
            int lz = code >> 6, ly = (code >> 3) & 7, lx = code & 7;
            const float* xp = &xs[lz*100 + ly*10 + lx];
            float acc = 0.f;
            #pragma unroll
            for (int dz = 0; dz < 3; dz++)
            #pragma unroll
            for (int dy = 0; dy < 3; dy++)
            #pragma unroll
            for (int dx = 0; dx < 3; dx++)
                acc = fmaf(xp[dz*100 + dy*10 + dx], w[(dz*3+dy)*3+dx], acc);
            acc = frelu(acc);
            int cell = ((lz>>1)<<4) | ((ly>>1)<<2) | (lx>>1);
            atomicMax((int*)&pl[cell*16 + ch], __float_as_int(acc)); // nonneg floats
        }
    }
    __syncthreads();

    #pragma unroll
    for (int it = 0; it < 4; it++) {
        int i = tid + it*256;
        int cell = i >> 4, c2 = i & 15;
        int cz = cell >> 4, cy = (cell >> 2) & 3, cx = cell & 3;
        int pz = tz*4 + cz, py = ty*4 + cy, px = tx*4 + cx;
        int pidx = ((b*H + pz)*H + py)*H + px;
        g_hp1[(pidx << 4) + c2] = pl[i];
        if (c2 == 0) g_m1[pidx] = (unsigned char)(cellact[cell] != 0);
    }
}

// ============================================================================
// K2: h2 = relu(conv3(hp1,W2))*m1; hp2 = maxpool2(h2); emits m2.
// 512 threads, 1 voxel/thread. Weights in CONSTANT memory read as packed
// f32 pairs with warp-uniform index (LDCU, off the smem crossbar);
// FFMA2 inner loop (co-pairs, input duplicated). Active-voxel compaction
// exploits m1 density (~57%). XOR-swizzled ts slots kill LDS bank conflicts.
// ============================================================================
__global__ __launch_bounds__(512) void k2_conv2_pool()
{
    extern __shared__ float ts[];            // 10*10*10*16 floats = 64000 B
    __shared__ float hs[512*4];              // per-voxel relu'd masked outputs
    __shared__ unsigned char sm1[512];       // per-voxel m1
    __shared__ unsigned short lst[512];      // compacted active voxels
    __shared__ int cnt;

    int bi  = blockIdx.x;
    int b   = bi >> 9;
    int t   = bi & 511;
    int tz  = t >> 6, ty = (t >> 3) & 7, tx = t & 7;
    int tid = threadIdx.x;

    if (tid == 0) cnt = 0;
    *(float4*)&hs[tid*4] = make_float4(0.f, 0.f, 0.f, 0.f);

    int fz0 = tz*8, fy0 = ty*8, fx0 = tx*8;

    // halo load with per-voxel XOR slot swizzle: data quad q -> slot q^(i&3)
    for (int i = tid; i < 1000; i += 512) {
        int z = i/100, y = (i/10)%10, xx = i%10;
        int gz = fz0+z-1, gy = fy0+y-1, gx = fx0+xx-1;
        float4* dst = (float4*)&ts[i*16];
        int s = i & 3;
        if ((unsigned)gz < H && (unsigned)gy < H && (unsigned)gx < H) {
            const float4* src = (const float4*)&g_hp1[(((b*H+gz)*H + gy)*H + gx)*16];
            dst[0^s] = src[0]; dst[1^s] = src[1]; dst[2^s] = src[2]; dst[3^s] = src[3];
        } else {
            float4 zz = make_float4(0.f, 0.f, 0.f, 0.f);
            dst[0] = zz; dst[1] = zz; dst[2] = zz; dst[3] = zz;
        }
    }

    // m1 + compaction
    {
        int lz = tid >> 6, ly = (tid >> 3) & 7, lx = tid & 7;
        int uz = fz0 + lz, uy = fy0 + ly, ux = fx0 + lx;
        unsigned char m1 = g_m1[((b*H + uz)*H + uy)*H + ux];
        sm1[tid] = m1;
        if (m1) {
            int p = atomicAdd(&cnt, 1);
            lst[p] = (unsigned short)tid;
        }
    }
    __syncthreads();

    int n = cnt;
    if (tid < n) {
        int code = lst[tid];
        int lz = code >> 6, ly = (code >> 3) & 7, lx = code & 7;

        unsigned long long a0 = 0ull, a1 = 0ull;   // (co0,co1),(co2,co3)

        #pragma unroll 1
        for (int dz = 0; dz < 3; dz++) {
            #pragma unroll 1
            for (int dy = 0; dy < 3; dy++) {
                int rowb = (lz+dz)*100 + (ly+dy)*10 + lx;
                int wb   = (dz*3 + dy)*3;
                #pragma unroll
                for (int dx = 0; dx < 3; dx++) {
                    int row = rowb + dx;
                    const float4* tp = (const float4*)&ts[row*16];
                    int s = row & 3;
                    const unsigned long long* wp =
                        (const unsigned long long*)&cW2[(wb + dx)*64];
                    #pragma unroll
                    for (int cq = 0; cq < 4; cq++) {
                        float v[4];
                        *(float4*)v = tp[cq ^ s];
                        #pragma unroll
                        for (int j = 0; j < 4; j++) {
                            unsigned long long d = dup2(v[j]);
                            fma2(a0, d, wp[(cq*4+j)*2 + 0]);
                            fma2(a1, d, wp[(cq*4+j)*2 + 1]);
                        }
                    }
                }
            }
        }
        float o0 = frelu(__uint_as_float((unsigned)(a0      )));
        float o1 = frelu(__uint_as_float((unsigned)(a0 >> 32)));
        float o2 = frelu(__uint_as_float((unsigned)(a1      )));
        float o3 = frelu(__uint_as_float((unsigned)(a1 >> 32)));
        *(float4*)&hs[code*4] = make_float4(o0, o1, o2, o3);
    }
    __syncthreads();

    // pool 2x2x2 + m2
    if (tid < 256) {
        int cell = tid >> 2, co = tid & 3;
        int cz = cell >> 4, cy = (cell >> 2) & 3, cx = cell & 3;
        float mv = 0.f;
        int anym = 0;
        #pragma unroll
        for (int k = 0; k < 8; k++) {
            int child = (((cz*2 + ((k>>2)&1)) << 6) |
                         ((cy*2 + ((k>>1)&1)) << 3) |
                          (cx*2 + (k&1)));
            mv = fmaxf(mv, hs[child*4 + co]);
            anym |= sm1[child];
        }
        int pz = tz*4 + cz, py = ty*4 + cy, px = tx*4 + cx;
        int cidx = ((b*Q + pz)*Q + py)*Q + px;
        g_hp2[cidx*4 + co] = mv;
        if (co == 0) g_m2[cidx] = (unsigned char)(anym != 0);
    }
}

// ============================================================================
// K3: fused decoder; m2 from g_m2 (no occ traffic). Direct float4 stores.
//   h3(2i+d,co) = relu(sum_ci hp2(i,ci)*Wt1[1-d][ci][co])   (conv_transpose flip)
//   out(2u+e)   = sigmoid(sum_co h3(u,co)*Wt2[1-e][co]) * m
// ============================================================================
__global__ __launch_bounds__(256) void k3_tconv(float* __restrict__ out)
{
    int gid = blockIdx.x*256 + threadIdx.x;
    int b  = gid >> 15;
    int c  = gid & 32767;
    int iz = c >> 10, iy = (c >> 5) & 31, ix = c & 31;

    int obase = ((b*G + 4*iz)*G + 4*iy)*G + 4*ix;

    if (!g_m2[gid]) {
        float4 zz = make_float4(0.f, 0.f, 0.f, 0.f);
        #pragma unroll
        for (int r = 0; r < 16; r++) {
            int wz = r >> 2, wy = r & 3;
            *(float4*)&out[obase + (wz*G + wy)*G] = zz;
        }
        return;
    }

    const float4 hin = *(const float4*)&g_hp2[gid*4];

    #pragma unroll
    for (int dz = 0; dz < 2; dz++)
    #pragma unroll
    for (int dy = 0; dy < 2; dy++) {
        float h3a[16], h3b[16];
        {
            const float* wA = &cWt1[(((1-dz)*2 + (1-dy))*2 + 1)*64]; // dx=0
            const float* wB = &cWt1[(((1-dz)*2 + (1-dy))*2 + 0)*64]; // dx=1
            #pragma unroll
            for (int co = 0; co < 16; co++) {
                float va = fmaf(hin.x, wA[co],
                           fmaf(hin.y, wA[16+co],
                           fmaf(hin.z, wA[32+co], hin.w * wA[48+co])));
                float vb = fmaf(hin.x, wB[co],
                           fmaf(hin.y, wB[16+co],
                           fmaf(hin.z, wB[32+co], hin.w * wB[48+co])));
                h3a[co] = frelu(va);
                h3b[co] = frelu(vb);
            }
        }
        #pragma unroll
        for (int ez = 0; ez < 2; ez++)
        #pragma unroll
        for (int ey = 0; ey < 2; ey++) {
            const float* w2e0 = &cWt2[((((1-ez)*2 + (1-ey))*2) + 1)*16]; // ex=0
            const float* w2e1 = &cWt2[((((1-ez)*2 + (1-ey))*2) + 0)*16]; // ex=1
            float sx = 0.f, sy = 0.f, sz = 0.f, sw = 0.f;
            #pragma unroll
            for (int co = 0; co < 16; co++) {
                sx = fmaf(h3a[co], w2e0[co], sx);
                sy = fmaf(h3a[co], w2e1[co], sy);
                sz = fmaf(h3b[co], w2e0[co], sz);
                sw = fmaf(h3b[co], w2e1[co], sw);
            }
            float4 o = make_float4(fsig(sx), fsig(sy), fsig(sz), fsig(sw));
            int wz = 2*dz + ez, wy = 2*dy + ey;
            *(float4*)&out[obase + (wz*G + wy)*G] = o;
        }
    }
}

// ============================================================================
extern "C" void kernel_launch(void* const* d_in, const int* in_sizes, int n_in,
                              void* d_out, int out_size)
{
    const float* x   = (const float*)d_in[0];
    const float* W1  = (const float*)d_in[1];
    const float* W2  = (const float*)d_in[2];
    const float* Wt1 = (const float*)d_in[3];
    const float* Wt2 = (const float*)d_in[4];
    const int*   occ = (const int*)  d_in[5];

    int B = in_sizes[0] / (G*G*G);

    cudaMemcpyToSymbolAsync(cW2,  W2,  3*3*3*16*4*sizeof(float), 0, cudaMemcpyDeviceToDevice, 0);
    cudaMemcpyToSymbolAsync(cWt1, Wt1, 2*2*2*4*16*sizeof(float), 0, cudaMemcpyDeviceToDevice, 0);
    cudaMemcpyToSymbolAsync(cWt2, Wt2, 2*2*2*16*sizeof(float),   0, cudaMemcpyDeviceToDevice, 0);

    cudaFuncSetAttribute(k2_conv2_pool, cudaFuncAttributeMaxDynamicSharedMemorySize, 64000);

    k1_conv1_pool<<<B*4096, 256>>>(x, occ, W1);
    k2_conv2_pool<<<B*512, 512, 64000>>>();
    k3_tconv<<<B*128, 256>>>((float*)d_out);
}